// round 9
// baseline (speedup 1.0000x reference)
#include <cuda_runtime.h>
#include <cstdint>
#include <cstddef>

// Shapes (fixed by the problem)
#define B 16
#define W 256
#define S 512
#define H 768
#define L 12
#define E 256

#define L_TMA 6                              // layers 0..5 via cp.async.bulk
#define L_LDG 6                              // layers 6..11 via LDG

#define LAYER_STRIDE ((size_t)B * S * H)     // elements between layers
#define ROW_BYTES (H * 4)                    // 3072 B per (l,b,s) row
#define ROW_F4    (ROW_BYTES / 16)           // 192 float4 per row
#define MAX_SLOTS (2 * L_TMA)                // up to 12 staged rows
#define SMEM_ROWS_BYTES (MAX_SLOTS * ROW_BYTES)   // 36864
#define SMEM_TOTAL (SMEM_ROWS_BYTES + 16)         // + mbarrier -> 6 blocks/SM

__device__ __forceinline__ uint32_t smem_u32(const void* p) {
    return (uint32_t)__cvta_generic_to_shared(p);
}

// Dual-path kernel: one block per (b,w) word, 192 threads.
//  - thread 0 stages layers [0,6) via cp.async.bulk (TMA path, mbarrier
//    transaction-byte completion, 3072 B per copy, 6*len copies)
//  - ALL threads simultaneously accumulate layers [6,12) via direct LDG.128
//    (12 independent loads per thread, dup-row trick for len==1)
//  - threads [0,64) also do the word-embedding gather
// Both memory paths (L1tex LDG queue + TMA bulk engine) are loaded at once.
__global__ __launch_bounds__(192)
void bert_lexer_kernel(const int* __restrict__ word_indices,
                       const int* __restrict__ span_start,
                       const int* __restrict__ span_end,
                       const float* __restrict__ W_embed,
                       const float* __restrict__ hidden,
                       float* __restrict__ out)
{
    extern __shared__ __align__(16) char smem[];
    const uint32_t mbar_addr = smem_u32(smem + SMEM_ROWS_BYTES);

    const int bw  = blockIdx.x;            // 0 .. B*W-1
    const int b   = bw >> 8;               // W = 256
    const int tid = threadIdx.x;           // 0 .. 191

    const int s0  = span_start[bw];
    const int se  = span_end[bw];
    const int sl  = se - 1;                // last position (== s0 if len==1)
    const int len = se - s0;               // 1 or 2

    if (tid == 0) {
        asm volatile("mbarrier.init.shared.b64 [%0], 1;" :: "r"(mbar_addr) : "memory");
        asm volatile("fence.proxy.async.shared::cta;" ::: "memory");
    }
    __syncthreads();

    // ---- TMA path: stage layers 0..5 ----
    if (tid == 0) {
        const uint32_t nbytes = (uint32_t)(L_TMA * len) * ROW_BYTES;
        asm volatile("mbarrier.arrive.expect_tx.shared.b64 _, [%0], %1;"
                     :: "r"(mbar_addr), "r"(nbytes) : "memory");
        const float* row0 = hidden + ((size_t)b * S + (size_t)s0) * H;
        uint32_t dst = smem_u32(smem);
        #pragma unroll
        for (int l = 0; l < L_TMA; ++l) {
            const float* src = row0 + (size_t)l * LAYER_STRIDE;
            asm volatile(
                "cp.async.bulk.shared::cta.global.mbarrier::complete_tx::bytes "
                "[%0], [%1], %2, [%3];"
                :: "r"(dst), "l"(src), "n"(ROW_BYTES), "r"(mbar_addr) : "memory");
            dst += ROW_BYTES;
            if (len == 2) {
                asm volatile(
                    "cp.async.bulk.shared::cta.global.mbarrier::complete_tx::bytes "
                    "[%0], [%1], %2, [%3];"
                    :: "r"(dst), "l"(src + H), "n"(ROW_BYTES), "r"(mbar_addr) : "memory");
                dst += ROW_BYTES;
            }
        }
    }

    // ---- overlap: word embedding gather (threads 0..63) ----
    float* orow = out + (size_t)bw * (E + H);
    if (tid < 64) {
        const int wi = word_indices[bw];
        float4 ev = __ldcs(reinterpret_cast<const float4*>(W_embed + (size_t)wi * E) + tid);
        __stcs(reinterpret_cast<float4*>(orow) + tid, ev);
    }

    // ---- LDG path: accumulate layers 6..11 directly ----
    const float* p0 = hidden + (size_t)L_TMA * LAYER_STRIDE
                             + ((size_t)b * S + (size_t)s0) * H + (size_t)tid * 4;
    const float* p1 = hidden + (size_t)L_TMA * LAYER_STRIDE
                             + ((size_t)b * S + (size_t)sl) * H + (size_t)tid * 4;

    float4 a0 = make_float4(0.f, 0.f, 0.f, 0.f);
    float4 a1 = make_float4(0.f, 0.f, 0.f, 0.f);
    #pragma unroll
    for (int l = 0; l < L_LDG; ++l) {
        float4 v0 = __ldcs(reinterpret_cast<const float4*>(p0 + (size_t)l * LAYER_STRIDE));
        float4 v1 = __ldcs(reinterpret_cast<const float4*>(p1 + (size_t)l * LAYER_STRIDE));
        a0.x += v0.x; a0.y += v0.y; a0.z += v0.z; a0.w += v0.w;
        a1.x += v1.x; a1.y += v1.y; a1.z += v1.z; a1.w += v1.w;
    }
    const float w1 = (len > 1) ? 1.0f : 0.0f;    // drop dup row when len==1
    float4 acc;
    acc.x = a0.x + w1 * a1.x;
    acc.y = a0.y + w1 * a1.y;
    acc.z = a0.z + w1 * a1.z;
    acc.w = a0.w + w1 * a1.w;

    // ---- wait for staged layers (acquire) ----
    {
        uint32_t done;
        asm volatile(
            "{\n\t.reg .pred p;\n\t"
            "mbarrier.try_wait.parity.acquire.cta.shared::cta.b64 p, [%1], %2, 0x989680;\n\t"
            "selp.b32 %0, 1, 0, p;\n\t}"
            : "=r"(done) : "r"(mbar_addr), "r"(0u) : "memory");
        if (!done) {
            asm volatile(
                "{\n\t.reg .pred P1;\n\t"
                "WAIT_LOOP:\n\t"
                "mbarrier.try_wait.parity.acquire.cta.shared::cta.b64 P1, [%0], %1, 0x989680;\n\t"
                "@P1 bra.uni WAIT_DONE;\n\t"
                "bra.uni WAIT_LOOP;\n\t"
                "WAIT_DONE:\n\t}"
                :: "r"(mbar_addr), "r"(0u) : "memory");
        }
    }

    // ---- reduce staged layers 0..5 from SMEM ----
    const int nslots = L_TMA * len;        // 6 or 12
    const float4* sp = reinterpret_cast<const float4*>(smem) + tid;
    #pragma unroll 6
    for (int i = 0; i < nslots; ++i) {
        float4 v = sp[(size_t)i * ROW_F4];
        acc.x += v.x; acc.y += v.y; acc.z += v.z; acc.w += v.w;
    }

    const float inv = 1.0f / (12.0f * (float)len);
    float4 r;
    r.x = acc.x * inv; r.y = acc.y * inv; r.z = acc.z * inv; r.w = acc.w * inv;
    __stcs(reinterpret_cast<float4*>(orow + E) + tid, r);
}

extern "C" void kernel_launch(void* const* d_in, const int* in_sizes, int n_in,
                              void* d_out, int out_size)
{
    const int*   word_indices = (const int*)  d_in[0];   // [B, W]
    const int*   span_start   = (const int*)  d_in[1];   // [B, W]
    const int*   span_end     = (const int*)  d_in[2];   // [B, W]
    const float* W_embed      = (const float*)d_in[3];   // [V, E]
    const float* hidden       = (const float*)d_in[4];   // [L, B, S, H]
    float*       out          = (float*)      d_out;     // [B, W, E+H]

    (void)in_sizes; (void)n_in; (void)out_size;

    cudaFuncSetAttribute(bert_lexer_kernel,
                         cudaFuncAttributeMaxDynamicSharedMemorySize, SMEM_TOTAL);

    bert_lexer_kernel<<<B * W, 192, SMEM_TOTAL>>>(word_indices, span_start,
                                                  span_end, W_embed, hidden, out);
}

// round 10
// speedup vs baseline: 1.1784x; 1.1784x over previous
#include <cuda_runtime.h>
#include <cstdint>
#include <cstddef>

// Shapes (fixed by the problem)
#define B 16
#define W 256
#define S 512
#define H 768
#define L 12
#define E 256

#define LAYER_STRIDE ((size_t)B * S * H)   // elements between layers
#define ROW_BYTES (H * 4)                  // 3072 bytes per (l,b,s) row
#define ROW_F4    (ROW_BYTES / 16)         // 192 float4 per row
#define MAX_SLOTS (2 * L)                  // up to 24 staged rows
#define SMEM_ROWS_BYTES (MAX_SLOTS * ROW_BYTES)   // 73728
#define SMEM_TOTAL (SMEM_ROWS_BYTES + 32)         // + two mbarriers

__device__ __forceinline__ uint32_t smem_u32(const void* p) {
    return (uint32_t)__cvta_generic_to_shared(p);
}

__device__ __forceinline__ void mbar_wait0(uint32_t mbar) {
    uint32_t done;
    asm volatile(
        "{\n\t.reg .pred p;\n\t"
        "mbarrier.try_wait.parity.acquire.cta.shared::cta.b64 p, [%1], %2, 0x989680;\n\t"
        "selp.b32 %0, 1, 0, p;\n\t}"
        : "=r"(done) : "r"(mbar), "r"(0u) : "memory");
    if (!done) {
        asm volatile(
            "{\n\t.reg .pred P1;\n\t"
            "WL_%=:\n\t"
            "mbarrier.try_wait.parity.acquire.cta.shared::cta.b64 P1, [%0], %1, 0x989680;\n\t"
            "@P1 bra.uni WD_%=;\n\t"
            "bra.uni WL_%=;\n\t"
            "WD_%=:\n\t}"
            :: "r"(mbar), "r"(0u) : "memory");
    }
}

// One block per (b,w) word, 192 threads (R5 champion + split-phase barrier).
// Thread 0 stages the span's 12*len hidden rows (3072 B bulk copies) with a
// SEPARATE mbarrier per span position, so the block reduces position 0's
// 12 rows while position 1's copies are still in flight. Threads [0,64)
// overlap the word-embedding gather with the copy latency.
__global__ __launch_bounds__(192)
void bert_lexer_kernel(const int* __restrict__ word_indices,
                       const int* __restrict__ span_start,
                       const int* __restrict__ span_end,
                       const float* __restrict__ W_embed,
                       const float* __restrict__ hidden,
                       float* __restrict__ out)
{
    extern __shared__ __align__(16) char smem[];
    const uint32_t mbar0 = smem_u32(smem + SMEM_ROWS_BYTES);       // pos 0
    const uint32_t mbar1 = mbar0 + 8;                              // pos 1

    const int bw  = blockIdx.x;            // 0 .. B*W-1
    const int b   = bw >> 8;               // W = 256
    const int tid = threadIdx.x;           // 0 .. 191

    const int s0  = span_start[bw];
    const int len = span_end[bw] - s0;     // 1 or 2

    if (tid == 0) {
        asm volatile("mbarrier.init.shared.b64 [%0], 1;" :: "r"(mbar0) : "memory");
        asm volatile("mbarrier.init.shared.b64 [%0], 1;" :: "r"(mbar1) : "memory");
        asm volatile("fence.proxy.async.shared::cta;" ::: "memory");
    }
    __syncthreads();

    if (tid == 0) {
        const float* row0 = hidden + ((size_t)b * S + (size_t)s0) * H;
        const uint32_t base = smem_u32(smem);

        // phase 0: 12 rows of span position s0
        asm volatile("mbarrier.arrive.expect_tx.shared.b64 _, [%0], %1;"
                     :: "r"(mbar0), "n"(L * ROW_BYTES) : "memory");
        #pragma unroll
        for (int l = 0; l < L; ++l) {
            asm volatile(
                "cp.async.bulk.shared::cta.global.mbarrier::complete_tx::bytes "
                "[%0], [%1], %2, [%3];"
                :: "r"(base + (uint32_t)l * ROW_BYTES),
                   "l"(row0 + (size_t)l * LAYER_STRIDE),
                   "n"(ROW_BYTES), "r"(mbar0) : "memory");
        }
        // phase 1: 12 rows of span position s0+1 (len==2 only)
        if (len == 2) {
            asm volatile("mbarrier.arrive.expect_tx.shared.b64 _, [%0], %1;"
                         :: "r"(mbar1), "n"(L * ROW_BYTES) : "memory");
            #pragma unroll
            for (int l = 0; l < L; ++l) {
                asm volatile(
                    "cp.async.bulk.shared::cta.global.mbarrier::complete_tx::bytes "
                    "[%0], [%1], %2, [%3];"
                    :: "r"(base + (uint32_t)(L + l) * ROW_BYTES),
                       "l"(row0 + H + (size_t)l * LAYER_STRIDE),
                       "n"(ROW_BYTES), "r"(mbar1) : "memory");
            }
        }
    }

    // ---- overlap: word embedding gather (threads 0..63) ----
    float* orow = out + (size_t)bw * (E + H);
    if (tid < 64) {
        const int wi = word_indices[bw];
        float4 ev = *(reinterpret_cast<const float4*>(W_embed + (size_t)wi * E) + tid);
        __stcs(reinterpret_cast<float4*>(orow) + tid, ev);
    }

    // ---- phase 0 reduce ----
    mbar_wait0(mbar0);
    const float4* sp = reinterpret_cast<const float4*>(smem) + tid;
    float4 acc = make_float4(0.f, 0.f, 0.f, 0.f);
    #pragma unroll
    for (int l = 0; l < L; ++l) {
        float4 v = sp[(size_t)l * ROW_F4];
        acc.x += v.x; acc.y += v.y; acc.z += v.z; acc.w += v.w;
    }

    // ---- phase 1 reduce (len==2 only) ----
    if (len == 2) {
        mbar_wait0(mbar1);
        const float4* sp1 = sp + (size_t)L * ROW_F4;
        #pragma unroll
        for (int l = 0; l < L; ++l) {
            float4 v = sp1[(size_t)l * ROW_F4];
            acc.x += v.x; acc.y += v.y; acc.z += v.z; acc.w += v.w;
        }
    }

    const float inv = 1.0f / (12.0f * (float)len);
    float4 r;
    r.x = acc.x * inv; r.y = acc.y * inv; r.z = acc.z * inv; r.w = acc.w * inv;
    __stcs(reinterpret_cast<float4*>(orow + E) + tid, r);
}

extern "C" void kernel_launch(void* const* d_in, const int* in_sizes, int n_in,
                              void* d_out, int out_size)
{
    const int*   word_indices = (const int*)  d_in[0];   // [B, W]
    const int*   span_start   = (const int*)  d_in[1];   // [B, W]
    const int*   span_end     = (const int*)  d_in[2];   // [B, W]
    const float* W_embed      = (const float*)d_in[3];   // [V, E]
    const float* hidden       = (const float*)d_in[4];   // [L, B, S, H]
    float*       out          = (float*)      d_out;     // [B, W, E+H]

    (void)in_sizes; (void)n_in; (void)out_size;

    cudaFuncSetAttribute(bert_lexer_kernel,
                         cudaFuncAttributeMaxDynamicSharedMemorySize, SMEM_TOTAL);

    bert_lexer_kernel<<<B * W, 192, SMEM_TOTAL>>>(word_indices, span_start,
                                                  span_end, W_embed, hidden, out);
}